// round 16
// baseline (speedup 1.0000x reference)
#include <cuda_runtime.h>
#include <cuda_fp16.h>
#include <cstdint>

// LocallyConnected2d, Round 12: R11 main kernel (unchanged) + rebuilt transforms.
//  xt: x[b][ci][rc] -> X_T[ci][rc][b] fp16   — float4 loads
//  wt: W[ci][o][loc][kk] -> B_T[loc][ci*9+kk][o] fp16 — 64-o tiles, full-line stores
//  main: per-loc GEMM D[64b x 64o], fp16 single-plane, cp.async staging
//  ot: OUT_T[loc][bo] -> out[bo][loc] — 64x64 float4 transpose

#define VSTRIDE 11520                 // one operand version: 80 rows x 144 B
#define DYN_SMEM (512 + 4 * VSTRIDE)  // bias + {AH,BH} x 2 buffers = 46592 B

__device__ __half X_T[(size_t)64 * 1024 * 64];       // 8.4 MB
__device__ __half B_T[(size_t)1024 * 576 * 64];      // 75.5 MB
__device__ float  OUT_T[(size_t)1024 * 4096];        // 16.8 MB  [loc][b*64+o]

static __device__ __forceinline__ uint32_t s2u(const void* p) {
    uint32_t a;
    asm("{ .reg .u64 t; cvta.to.shared.u64 t, %1; cvt.u32.u64 %0, t; }"
        : "=r"(a) : "l"(p));
    return a;
}

static __device__ __forceinline__ void ldsm4t(uint32_t addr, uint32_t* r) {
    asm volatile("ldmatrix.sync.aligned.m8n8.x4.trans.shared.b16 {%0,%1,%2,%3}, [%4];"
                 : "=r"(r[0]), "=r"(r[1]), "=r"(r[2]), "=r"(r[3]) : "r"(addr));
}

static __device__ __forceinline__ void mma_f16(float* d, const uint32_t* a,
                                               const uint32_t* b) {
    asm volatile("mma.sync.aligned.m16n8k16.row.col.f32.f16.f16.f32 "
                 "{%0,%1,%2,%3}, {%4,%5,%6,%7}, {%8,%9}, {%0,%1,%2,%3};"
                 : "+f"(d[0]), "+f"(d[1]), "+f"(d[2]), "+f"(d[3])
                 : "r"(a[0]), "r"(a[1]), "r"(a[2]), "r"(a[3]),
                   "r"(b[0]), "r"(b[1]));
}

static __device__ __forceinline__ uint32_t pack_h2(float v0, float v1) {
    __half h0 = __float2half_rn(v0), h1 = __float2half_rn(v1);
    return (uint32_t)*(uint16_t*)&h0 | ((uint32_t)*(uint16_t*)&h1 << 16);
}

// ---- x transform: [b][ci][rc] f32 -> X_T[ci][rc][b] fp16 (float4 loads) ----
__global__ __launch_bounds__(256)
void xt_kernel(const float* __restrict__ x)
{
    __shared__ float tile[64][129];   // [b][rc_local], pad 129 -> 2-way LDS max
    const int ci  = blockIdx.x >> 3;
    const int rc0 = (blockIdx.x & 7) * 128;
    const int tid = threadIdx.x;
    #pragma unroll
    for (int i = 0; i < 8; i++) {     // 2048 f4 = 64 b x 32 f4
        int q = tid + 256 * i;
        int b = q >> 5, j = q & 31;
        float4 v = *(const float4*)(x + (size_t)b * 65536 + ci * 1024 + rc0 + 4 * j);
        tile[b][4 * j + 0] = v.x;
        tile[b][4 * j + 1] = v.y;
        tile[b][4 * j + 2] = v.z;
        tile[b][4 * j + 3] = v.w;
    }
    __syncthreads();
    #pragma unroll
    for (int i = 0; i < 16; i++) {    // 4096 = 128 rc-rows x 32 lp
        int q = tid + 256 * i;
        int row = q >> 5, lp = q & 31;
        uint32_t pk = pack_h2(tile[2 * lp][row], tile[2 * lp + 1][row]);
        *(uint32_t*)&X_T[((size_t)ci * 1024 + rc0 + row) * 64 + 2 * lp] = pk;
    }
}

// ---- W transform: [ci][o][loc][kk] f32 -> B_T[loc][ci*9+kk][o] fp16 ----
// 64-o x 16-loc tiles: every B_T row (128B) stored as one full line by one warp.
__global__ __launch_bounds__(256)
void wt_kernel(const float* __restrict__ wgt)
{
    __shared__ float tile[64][145];   // [o][loc_l*9+kk], pad 145 -> 2-way LDS max
    const int ci   = blockIdx.x >> 6;
    const int loc0 = (blockIdx.x & 63) * 16;
    const int tid  = threadIdx.x;
    #pragma unroll
    for (int i = 0; i < 9; i++) {     // 2304 f4 = 64 o x 36 f4 (144 floats/row)
        int q = tid + 256 * i;
        int o = q / 36, j = q % 36;
        float4 v = *(const float4*)(wgt + (size_t)(ci * 64 + o) * 9216
                                        + loc0 * 9 + 4 * j);
        tile[o][4 * j + 0] = v.x;
        tile[o][4 * j + 1] = v.y;
        tile[o][4 * j + 2] = v.z;
        tile[o][4 * j + 3] = v.w;
    }
    __syncthreads();
    #pragma unroll
    for (int i = 0; i < 18; i++) {    // 4608 = 144 rows x 32 lp (full 128B line/row)
        int q = tid + 256 * i;
        int row = q >> 5, lp = q & 31;
        uint32_t pk = pack_h2(tile[2 * lp][row], tile[2 * lp + 1][row]);
        const int loc = loc0 + row / 9;
        const int k   = ci * 9 + row % 9;
        *(uint32_t*)&B_T[((size_t)loc * 576 + k) * 64 + 2 * lp] = pk;
    }
}

// ---- output transpose: OUT_T[loc][bo] -> out[bo][loc], float4 both sides ----
__global__ __launch_bounds__(256)
void ot_kernel(float* __restrict__ out)
{
    __shared__ float tile[64][65];    // [loc_l][bo_l], pad 65 -> 2-way LDS max
    const int loc0 = (blockIdx.x & 15) * 64;
    const int bo0  = (blockIdx.x >> 4) * 64;
    const int tid  = threadIdx.x;
    #pragma unroll
    for (int i = 0; i < 4; i++) {     // 1024 f4 = 64 loc x 16 f4
        int q = tid + 256 * i;
        int l = q >> 4, j = q & 15;
        float4 v = *(const float4*)(&OUT_T[(size_t)(loc0 + l) * 4096 + bo0 + 4 * j]);
        tile[l][4 * j + 0] = v.x;
        tile[l][4 * j + 1] = v.y;
        tile[l][4 * j + 2] = v.z;
        tile[l][4 * j + 3] = v.w;
    }
    __syncthreads();
    #pragma unroll
    for (int i = 0; i < 4; i++) {     // 1024 f4 = 64 bo x 16 f4(loc)
        int q = tid + 256 * i;
        int bo = q >> 4, j = q & 15;
        float4 v;
        v.x = tile[4 * j + 0][bo];
        v.y = tile[4 * j + 1][bo];
        v.z = tile[4 * j + 2][bo];
        v.w = tile[4 * j + 3][bo];
        *(float4*)(out + (size_t)(bo0 + bo) * 1024 + loc0 + 4 * j) = v;
    }
}

// ---- main GEMM kernel (unchanged from R11) ----
__global__ __launch_bounds__(256, 4)
void lc2d_mma_kernel(const float* __restrict__ bias)
{
    extern __shared__ char sm[];
    const uint32_t sb = s2u(sm);
    const int tid  = threadIdx.x;
    const int wid  = tid >> 5;
    const int lane = tid & 31;
    const int h = blockIdx.x >> 5;
    const int w = blockIdx.x & 31;
    const int loc = h * 32 + w;

    float* biasS = (float*)sm;
    if (tid < 64) biasS[tid] = bias[tid * 1024 + loc];

    // Zero pad rows k=72..79 of all 4 operand versions (never overwritten).
    for (int q = tid; q < 1152; q += 256) {
        const int vi = q / 288, rr = q % 288;
        *(float*)(sm + 512 + vi * VSTRIDE + (72 + rr / 36) * 144 + (rr % 36) * 4) = 0.f;
    }

    // cp.async staging: 1152 16B ops per chunk ({A,B} x 72 k-rows x 8 frags)
    auto stage = [&](int chunk, int buf) {
        const uint32_t vb = sb + 512 + (uint32_t)buf * 2 * VSTRIDE;
        #pragma unroll
        for (int i = 0; i < 5; i++) {
            const int op = tid + 256 * i;
            if (op >= 1152) break;
            const int frag = op & 7;
            const int seg = op >> 3;           // 0..143
            const __half* src;
            uint32_t dst;
            int sz = 16;
            if (seg < 72) {                    // A
                const int k = seg;
                const int ci = chunk * 8 + k / 9;
                const int t9 = k % 9;
                int r = h - 1 + t9 / 3;
                int c = w - 1 + t9 % 3;
                if ((unsigned)r >= 32u || (unsigned)c >= 32u) { sz = 0; r = 0; c = 0; }
                src = X_T + (((size_t)ci * 1024 + r * 32 + c) * 64 + frag * 8);
                dst = vb + (uint32_t)(k * 144 + frag * 16);
            } else {                           // B
                const int k = seg - 72;
                const int kg = chunk * 72 + k;
                src = B_T + (((size_t)loc * 576 + kg) * 64 + frag * 8);
                dst = vb + (uint32_t)(VSTRIDE + k * 144 + frag * 16);
            }
            asm volatile("cp.async.cg.shared.global [%0], [%1], 16, %2;"
                         :: "r"(dst), "l"(src), "r"(sz) : "memory");
        }
    };

    // ldmatrix.x4.trans lane geometry (verified R5-R11).
    const int blk = lane >> 3, rin = lane & 7;
    const uint32_t aoff = (uint32_t)(((blk >> 1) * 8 + rin) * 144 + ((blk & 1) * 8) * 2);
    const uint32_t boff = (uint32_t)(((blk & 1) * 8 + rin) * 144 + ((blk >> 1) * 8) * 2);
    const int wm = (wid >> 2) * 32;   // warp M base
    const int wn = (wid & 3) * 16;    // warp N base

    float acc[2][2][4];
    #pragma unroll
    for (int i = 0; i < 2; i++)
        #pragma unroll
        for (int j = 0; j < 2; j++)
            #pragma unroll
            for (int k = 0; k < 4; k++)
                acc[i][j][k] = 0.f;

    stage(0, 0);
    asm volatile("cp.async.commit_group;" ::: "memory");

    for (int c = 0; c < 8; c++) {
        if (c < 7) {
            stage(c + 1, (c + 1) & 1);
            asm volatile("cp.async.commit_group;" ::: "memory");
            asm volatile("cp.async.wait_group 1;" ::: "memory");
        } else {
            asm volatile("cp.async.wait_group 0;" ::: "memory");
        }
        __syncthreads();

        const uint32_t vb = sb + 512 + (uint32_t)(c & 1) * 2 * VSTRIDE;
        const uint32_t AH = vb, BH = vb + VSTRIDE;

        #pragma unroll
        for (int ks = 0; ks < 5; ks++) {
            const uint32_t kb = (uint32_t)(ks * 16 * 144);
            uint32_t ah[2][4], bh[4];
            #pragma unroll
            for (int mt = 0; mt < 2; mt++)
                ldsm4t(AH + kb + aoff + (uint32_t)((wm + mt * 16) * 2), ah[mt]);
            ldsm4t(BH + kb + boff + (uint32_t)(wn * 2), bh);
            #pragma unroll
            for (int mt = 0; mt < 2; mt++)
                #pragma unroll
                for (int nt = 0; nt < 2; nt++)
                    mma_f16(acc[mt][nt], ah[mt], &bh[nt * 2]);
        }
        __syncthreads();
    }

    // Epilogue: coalesced STG.64 into OUT_T[loc][b*64+o].
    const int g = lane >> 2, t2 = lane & 3;
    float* ob = OUT_T + (size_t)loc * 4096;
    #pragma unroll
    for (int mt = 0; mt < 2; mt++)
        #pragma unroll
        for (int nt = 0; nt < 2; nt++)
            #pragma unroll
            for (int rp = 0; rp < 2; rp++) {
                const int b = wm + mt * 16 + g + rp * 8;
                const int o = wn + nt * 8 + t2 * 2;
                float2 v;
                v.x = acc[mt][nt][rp * 2 + 0] + biasS[o];
                v.y = acc[mt][nt][rp * 2 + 1] + biasS[o + 1];
                *(float2*)(ob + b * 64 + o) = v;
            }
}

extern "C" void kernel_launch(void* const* d_in, const int* in_sizes, int n_in,
                              void* d_out, int out_size)
{
    const float* x    = (const float*)d_in[0];
    const float* wgt  = (const float*)d_in[1];
    const float* bias = (const float*)d_in[2];
    float* out        = (float*)d_out;

    cudaFuncSetAttribute(lc2d_mma_kernel,
                         cudaFuncAttributeMaxDynamicSharedMemorySize, DYN_SMEM);

    xt_kernel<<<512, 256>>>(x);
    wt_kernel<<<4096, 256>>>(wgt);
    lc2d_mma_kernel<<<1024, 256, DYN_SMEM>>>(bias);
    ot_kernel<<<1024, 256>>>(out);
}